// round 1
// baseline (speedup 1.0000x reference)
#include <cuda_runtime.h>
#include <cstdint>

#define N_ATOMS_MAX 2000000
#define N_MOL_MAX   50000

#define TILE_M   128
#define K_DIM    128
#define N_DIM    64
#define XS_PITCH 132   // 132 % 32 == 4 -> conflict-free A-fragment loads
#define WS_PITCH 72    // 72  % 32 == 8 -> conflict-free B-fragment loads

// scratch (no device allocation allowed)
__device__ float g_atom_out[N_ATOMS_MAX];
__device__ float g_corr[N_MOL_MAX];

__device__ __forceinline__ uint32_t f2tf32(float f) {
    uint32_t u;
    asm("cvt.rna.tf32.f32 %0, %1;" : "=r"(u) : "f"(f));
    return u;
}

__device__ __forceinline__ float silu(float v) {
    return __fdividef(v, 1.0f + __expf(-v));
}

// ---------------------------------------------------------------------------
// Kernel 1: per-atom MLP  atom_out = silu(x@W1 + b1) @ W2 + b2
// One block = 128 atoms. tf32 tensor-core GEMM, fused epilogue.
// ---------------------------------------------------------------------------
__global__ __launch_bounds__(256, 2)
void mlp_kernel(const float* __restrict__ x,
                const float* __restrict__ W1,
                const float* __restrict__ b1,
                const float* __restrict__ W2,
                const float* __restrict__ b2,
                int n_atoms)
{
    extern __shared__ uint32_t smem[];
    uint32_t* Xs = smem;                            // [128][132] tf32
    uint32_t* Ws = smem + TILE_M * XS_PITCH;        // [128][72]  tf32
    float* b1s = (float*)(Ws + K_DIM * WS_PITCH);   // [64]
    float* w2s = b1s + N_DIM;                       // [64]

    const int tid  = threadIdx.x;
    const long base = (long)blockIdx.x * TILE_M;

    // ---- stage X tile (coalesced float4, convert to tf32 with RN) ----
    #pragma unroll
    for (int i = 0; i < 16; i++) {
        int idx = tid + 256 * i;           // 0..4095 float4 slots
        int row = idx >> 5;                // 32 float4 per row
        int c4  = idx & 31;
        long grow = base + row;
        float4 v = (grow < n_atoms)
                 ? ((const float4*)(x + grow * (long)K_DIM))[c4]
                 : make_float4(0.f, 0.f, 0.f, 0.f);
        uint32_t* d = &Xs[row * XS_PITCH + (c4 << 2)];
        d[0] = f2tf32(v.x); d[1] = f2tf32(v.y);
        d[2] = f2tf32(v.z); d[3] = f2tf32(v.w);
    }
    // ---- stage W1 [128 x 64] ----
    #pragma unroll
    for (int i = 0; i < 8; i++) {
        int idx = tid + 256 * i;           // 0..2047 float4 slots
        int row = idx >> 4;                // 16 float4 per row
        int c4  = idx & 15;
        float4 v = ((const float4*)(W1 + row * N_DIM))[c4];
        uint32_t* d = &Ws[row * WS_PITCH + (c4 << 2)];
        d[0] = f2tf32(v.x); d[1] = f2tf32(v.y);
        d[2] = f2tf32(v.z); d[3] = f2tf32(v.w);
    }
    if (tid < N_DIM) { b1s[tid] = b1[tid]; w2s[tid] = W2[tid]; }
    __syncthreads();

    // ---- warp tile: 16 rows x 64 cols, K=128 via 16 x m16n8k8 ----
    const int lane = tid & 31, warp = tid >> 5;
    const int g = lane >> 2, tq = lane & 3;
    const int r0 = warp * 16;

    float c[8][4];
    #pragma unroll
    for (int nt = 0; nt < 8; nt++)
        { c[nt][0] = 0.f; c[nt][1] = 0.f; c[nt][2] = 0.f; c[nt][3] = 0.f; }

    #pragma unroll
    for (int kk = 0; kk < 16; kk++) {
        const int k0 = kk * 8;
        uint32_t a0 = Xs[(r0 + g    ) * XS_PITCH + k0 + tq    ];
        uint32_t a1 = Xs[(r0 + g + 8) * XS_PITCH + k0 + tq    ];
        uint32_t a2 = Xs[(r0 + g    ) * XS_PITCH + k0 + tq + 4];
        uint32_t a3 = Xs[(r0 + g + 8) * XS_PITCH + k0 + tq + 4];
        #pragma unroll
        for (int nt = 0; nt < 8; nt++) {
            uint32_t bb0 = Ws[(k0 + tq    ) * WS_PITCH + nt * 8 + g];
            uint32_t bb1 = Ws[(k0 + tq + 4) * WS_PITCH + nt * 8 + g];
            asm("mma.sync.aligned.m16n8k8.row.col.f32.tf32.tf32.f32 "
                "{%0,%1,%2,%3}, {%4,%5,%6,%7}, {%8,%9}, {%0,%1,%2,%3};"
                : "+f"(c[nt][0]), "+f"(c[nt][1]), "+f"(c[nt][2]), "+f"(c[nt][3])
                : "r"(a0), "r"(a1), "r"(a2), "r"(a3), "r"(bb0), "r"(bb1));
        }
    }

    // ---- epilogue: +b1, silu, dot with W2, reduce over 4 lanes of row group ----
    const float b2v = b2[0];
    float sA = 0.f, sB = 0.f;
    #pragma unroll
    for (int nt = 0; nt < 8; nt++) {
        int col0 = nt * 8 + tq * 2;
        int col1 = col0 + 1;
        sA += silu(c[nt][0] + b1s[col0]) * w2s[col0];
        sA += silu(c[nt][1] + b1s[col1]) * w2s[col1];
        sB += silu(c[nt][2] + b1s[col0]) * w2s[col0];
        sB += silu(c[nt][3] + b1s[col1]) * w2s[col1];
    }
    sA += __shfl_xor_sync(0xFFFFFFFFu, sA, 1);
    sA += __shfl_xor_sync(0xFFFFFFFFu, sA, 2);
    sB += __shfl_xor_sync(0xFFFFFFFFu, sB, 1);
    sB += __shfl_xor_sync(0xFFFFFFFFu, sB, 2);

    if (tq == 0) {
        long rA = base + r0 + g;
        long rB = rA + 8;
        if (rA < n_atoms) g_atom_out[rA] = sA + b2v;
        if (rB < n_atoms) g_atom_out[rB] = sB + b2v;
    }
}

// ---------------------------------------------------------------------------
// Kernel 2: per-molecule segment sum over sorted batch (deterministic,
// binary search for segment start), store correction term.
// ---------------------------------------------------------------------------
__global__ void seg_kernel(const int* __restrict__ batch,
                           const float* __restrict__ charge,
                           int n_atoms, int n_mol)
{
    int m = blockIdx.x * blockDim.x + threadIdx.x;
    if (m >= n_mol) return;
    // lower_bound
    int lo = 0, hi = n_atoms;
    while (lo < hi) {
        int mid = (lo + hi) >> 1;
        if (batch[mid] < m) lo = mid + 1; else hi = mid;
    }
    float s = 0.f;
    int cnt = 0;
    int i = lo;
    while (i < n_atoms && batch[i] == m) {
        s += g_atom_out[i];
        cnt++; i++;
    }
    g_corr[m] = (cnt > 0) ? (charge[m] - s) / (float)cnt : 0.f;
}

// ---------------------------------------------------------------------------
// Kernel 3: final gather
// ---------------------------------------------------------------------------
__global__ void out_kernel(const int* __restrict__ batch,
                           float* __restrict__ out, int n_atoms)
{
    int i = blockIdx.x * blockDim.x + threadIdx.x;
    if (i < n_atoms) out[i] = g_atom_out[i] + g_corr[batch[i]];
}

// ---------------------------------------------------------------------------
extern "C" void kernel_launch(void* const* d_in, const int* in_sizes, int n_in,
                              void* d_out, int out_size)
{
    const float* x      = (const float*)d_in[0];
    const int*   batch  = (const int*)  d_in[1];
    const float* charge = (const float*)d_in[2];
    const float* W1     = (const float*)d_in[3];
    const float* b1     = (const float*)d_in[4];
    const float* W2     = (const float*)d_in[5];
    const float* b2     = (const float*)d_in[6];
    float* out = (float*)d_out;

    const int n_atoms = in_sizes[0] / K_DIM;
    const int n_mol   = in_sizes[2];

    const int smem_bytes = (TILE_M * XS_PITCH + K_DIM * WS_PITCH + 2 * N_DIM) * 4;
    cudaFuncSetAttribute(mlp_kernel, cudaFuncAttributeMaxDynamicSharedMemorySize,
                         smem_bytes);

    int grid1 = (n_atoms + TILE_M - 1) / TILE_M;
    mlp_kernel<<<grid1, 256, smem_bytes>>>(x, W1, b1, W2, b2, n_atoms);

    seg_kernel<<<(n_mol + 255) / 256, 256>>>(batch, charge, n_atoms, n_mol);

    out_kernel<<<(n_atoms + 255) / 256, 256>>>(batch, out, n_atoms);
}

// round 3
// speedup vs baseline: 1.1760x; 1.1760x over previous
#include <cuda_runtime.h>
#include <cstdint>

#define N_ATOMS_MAX 2000000
#define N_MOL_MAX   50000

#define K_DIM   128
#define N_DIM   64
#define TILE_M  128
#define XPITCH  68     // floats per row of half-K buffer (64 + 4 pad) -> conflict-free A reads
#define GRID_P  304    // 2 blocks per SM on 152-SM GB300

// smem layout (in floats):
//   Xb[2][128*68]      : 0     .. 17408
//   Bf[10240] (u32)    : 17408 .. 27648   (fragment-major tf32 W1, stride 20/lane)
//   b1s[64]            : 27648
//   w2s[64]            : 27712
#define SMEM_FLOATS 27776
#define XBUF_FLOATS 8704   // 128*68

// scratch (no device allocation allowed)
__device__ float g_atom_out[N_ATOMS_MAX];
__device__ float g_corr[N_MOL_MAX];

__device__ __forceinline__ uint32_t f2tf32(float f) {
    uint32_t u;
    asm("cvt.rna.tf32.f32 %0, %1;" : "=r"(u) : "f"(f));
    return u;
}
__device__ __forceinline__ float silu(float v) {
    return __fdividef(v, 1.0f + __expf(-v));
}
__device__ __forceinline__ void cp16(uint32_t daddr, const void* gptr, uint32_t sz) {
    asm volatile("cp.async.cg.shared.global [%0], [%1], 16, %2;"
                 :: "r"(daddr), "l"(gptr), "r"(sz));
}
#define MMA_TF32(C, A0, A1, A2, A3, B0, B1)                                   \
    asm("mma.sync.aligned.m16n8k8.row.col.f32.tf32.tf32.f32 "                 \
        "{%0,%1,%2,%3}, {%4,%5,%6,%7}, {%8,%9}, {%0,%1,%2,%3};"               \
        : "+f"(C[0]), "+f"(C[1]), "+f"(C[2]), "+f"(C[3])                      \
        : "r"(A0), "r"(A1), "r"(A2), "r"(A3), "r"(B0), "r"(B1))

// ---------------------------------------------------------------------------
// Kernel 1: persistent per-atom MLP with cp.async ring pipeline.
// ---------------------------------------------------------------------------
__global__ __launch_bounds__(256, 2)
void mlp_kernel(const float* __restrict__ x,
                const float* __restrict__ W1,
                const float* __restrict__ b1,
                const float* __restrict__ W2,
                const float* __restrict__ b2,
                int n_atoms, int ntiles)
{
    extern __shared__ float smem[];
    float*    Xb  = smem;
    uint32_t* Bf  = (uint32_t*)(smem + 2 * XBUF_FLOATS);
    float*    b1s = smem + 27648;
    float*    w2s = smem + 27712;
    const uint32_t smem_base = (uint32_t)__cvta_generic_to_shared(smem);

    const int tid  = threadIdx.x;
    const int lane = tid & 31, warp = tid >> 5;
    const int g = lane >> 2, tq = lane & 3;
    const int r0 = warp * 16;

    // ---- stage W1 once: tf32, fragment-major [kk][lane(stride 20)][nt*2+j] ----
    #pragma unroll
    for (int i = 0; i < 32; i++) {
        int e = tid + 256 * i;               // e = k*64 + n  (coalesced read)
        int k = e >> 6, n = e & 63;
        uint32_t v = f2tf32(W1[e]);
        int gg = n & 7, nt = n >> 3, kk = k >> 3, kb = k & 7;
        int tq2 = kb & 3, j = nt * 2 + (kb >> 2);
        Bf[kk * 640 + (gg * 4 + tq2) * 20 + j] = v;
    }
    if (tid < N_DIM) { b1s[tid] = b1[tid]; w2s[tid] = W2[tid]; }
    const float b2v = b2[0];

    const int nloc = (blockIdx.x < ntiles) ? (ntiles - blockIdx.x + GRID_P - 1) / GRID_P : 0;
    const int C = nloc * 2;                  // chunks: (tile, half-K)
    __syncthreads();
    if (C <= 0) return;

    // ---- prefetch chunk 0 ----
    {
        long rowbase = (long)blockIdx.x * TILE_M;
        const float* src = x + rowbase * K_DIM;   // half 0
        uint32_t dbase = smem_base;
        #pragma unroll
        for (int i = 0; i < 8; i++) {
            int ch = tid + 256 * i;
            int row = ch >> 4, c16 = ch & 15;
            uint32_t sz = (rowbase + row < n_atoms) ? 16u : 0u;
            const float* s = sz ? (src + (long)row * K_DIM + c16 * 4) : x;
            cp16(dbase + (uint32_t)(row * XPITCH + c16 * 4) * 4u, s, sz);
        }
    }
    asm volatile("cp.async.commit_group;");

    float acc[8][4];

    for (int c = 0; c < C; c++) {
        // prefetch chunk c+1 into the other buffer
        if (c + 1 < C) {
            int cn = c + 1;
            long tile = (long)blockIdx.x + (long)(cn >> 1) * GRID_P;
            long rowbase = tile * TILE_M;
            const float* src = x + rowbase * K_DIM + (cn & 1) * 64;
            uint32_t dbase = smem_base + (uint32_t)((cn & 1) * XBUF_FLOATS) * 4u;
            #pragma unroll
            for (int i = 0; i < 8; i++) {
                int ch = tid + 256 * i;
                int row = ch >> 4, c16 = ch & 15;
                uint32_t sz = (rowbase + row < n_atoms) ? 16u : 0u;
                const float* s = sz ? (src + (long)row * K_DIM + c16 * 4) : x;
                cp16(dbase + (uint32_t)(row * XPITCH + c16 * 4) * 4u, s, sz);
            }
        }
        asm volatile("cp.async.commit_group;");
        asm volatile("cp.async.wait_group 1;");
        __syncthreads();

        const int half = c & 1;
        const float* Xc = Xb + half * XBUF_FLOATS;

        if (half == 0) {
            #pragma unroll
            for (int nt = 0; nt < 8; nt++) {
                acc[nt][0] = 0.f; acc[nt][1] = 0.f;
                acc[nt][2] = 0.f; acc[nt][3] = 0.f;
            }
        }

        #pragma unroll
        for (int kkl = 0; kkl < 8; kkl++) {
            const float* ar = Xc + (r0 + g) * XPITCH + kkl * 8 + tq;
            uint32_t a0 = f2tf32(ar[0]);
            uint32_t a2 = f2tf32(ar[4]);
            uint32_t a1 = f2tf32(ar[8 * XPITCH]);
            uint32_t a3 = f2tf32(ar[8 * XPITCH + 4]);
            const uint32_t* bp = Bf + (half * 8 + kkl) * 640 + lane * 20;
            uint4 b01 = *(const uint4*)(bp);
            uint4 b23 = *(const uint4*)(bp + 4);
            uint4 b45 = *(const uint4*)(bp + 8);
            uint4 b67 = *(const uint4*)(bp + 12);
            MMA_TF32(acc[0], a0, a1, a2, a3, b01.x, b01.y);
            MMA_TF32(acc[1], a0, a1, a2, a3, b01.z, b01.w);
            MMA_TF32(acc[2], a0, a1, a2, a3, b23.x, b23.y);
            MMA_TF32(acc[3], a0, a1, a2, a3, b23.z, b23.w);
            MMA_TF32(acc[4], a0, a1, a2, a3, b45.x, b45.y);
            MMA_TF32(acc[5], a0, a1, a2, a3, b45.z, b45.w);
            MMA_TF32(acc[6], a0, a1, a2, a3, b67.x, b67.y);
            MMA_TF32(acc[7], a0, a1, a2, a3, b67.z, b67.w);
        }

        if (half == 1) {
            // epilogue: +b1, silu, dot W2, reduce over tq lanes, store
            float sA = 0.f, sB = 0.f;
            #pragma unroll
            for (int nt = 0; nt < 8; nt++) {
                int col0 = nt * 8 + tq * 2;
                int col1 = col0 + 1;
                sA += silu(acc[nt][0] + b1s[col0]) * w2s[col0];
                sA += silu(acc[nt][1] + b1s[col1]) * w2s[col1];
                sB += silu(acc[nt][2] + b1s[col0]) * w2s[col0];
                sB += silu(acc[nt][3] + b1s[col1]) * w2s[col1];
            }
            sA += __shfl_xor_sync(0xFFFFFFFFu, sA, 1);
            sA += __shfl_xor_sync(0xFFFFFFFFu, sA, 2);
            sB += __shfl_xor_sync(0xFFFFFFFFu, sB, 1);
            sB += __shfl_xor_sync(0xFFFFFFFFu, sB, 2);
            if (tq == 0) {
                long tile = (long)blockIdx.x + (long)(c >> 1) * GRID_P;
                long rA = tile * TILE_M + r0 + g;
                long rB = rA + 8;
                if (rA < n_atoms) g_atom_out[rA] = sA + b2v;
                if (rB < n_atoms) g_atom_out[rB] = sB + b2v;
            }
        }
        __syncthreads();
    }
}

// ---------------------------------------------------------------------------
// Kernel 2: per-molecule segment sum over sorted batch (deterministic).
// ---------------------------------------------------------------------------
__global__ void seg_kernel(const int* __restrict__ batch,
                           const float* __restrict__ charge,
                           int n_atoms, int n_mol)
{
    int m = blockIdx.x * blockDim.x + threadIdx.x;
    if (m >= n_mol) return;
    int lo = 0, hi = n_atoms;
    while (lo < hi) {
        int mid = (lo + hi) >> 1;
        if (batch[mid] < m) lo = mid + 1; else hi = mid;
    }
    float s = 0.f;
    int cnt = 0;
    int i = lo;
    while (i < n_atoms && batch[i] == m) {
        s += g_atom_out[i];
        cnt++; i++;
    }
    g_corr[m] = (cnt > 0) ? (charge[m] - s) / (float)cnt : 0.f;
}

// ---------------------------------------------------------------------------
// Kernel 3: final gather
// ---------------------------------------------------------------------------
__global__ void out_kernel(const int* __restrict__ batch,
                           float* __restrict__ out, int n_atoms)
{
    int i = blockIdx.x * blockDim.x + threadIdx.x;
    if (i < n_atoms) out[i] = g_atom_out[i] + g_corr[batch[i]];
}

// ---------------------------------------------------------------------------
extern "C" void kernel_launch(void* const* d_in, const int* in_sizes, int n_in,
                              void* d_out, int out_size)
{
    const float* x      = (const float*)d_in[0];
    const int*   batch  = (const int*)  d_in[1];
    const float* charge = (const float*)d_in[2];
    const float* W1     = (const float*)d_in[3];
    const float* b1     = (const float*)d_in[4];
    const float* W2     = (const float*)d_in[5];
    const float* b2     = (const float*)d_in[6];
    float* out = (float*)d_out;

    const int n_atoms = in_sizes[0] / K_DIM;
    const int n_mol   = in_sizes[2];
    const int ntiles  = (n_atoms + TILE_M - 1) / TILE_M;

    const int smem_bytes = SMEM_FLOATS * 4;
    cudaFuncSetAttribute(mlp_kernel, cudaFuncAttributeMaxDynamicSharedMemorySize,
                         smem_bytes);

    mlp_kernel<<<GRID_P, 256, smem_bytes>>>(x, W1, b1, W2, b2, n_atoms, ntiles);
    seg_kernel<<<(n_mol + 255) / 256, 256>>>(batch, charge, n_atoms, n_mol);
    out_kernel<<<(n_atoms + 255) / 256, 256>>>(batch, out, n_atoms);
}

// round 4
// speedup vs baseline: 1.3928x; 1.1844x over previous
#include <cuda_runtime.h>
#include <cuda.h>
#include <cstdint>

#define N_ATOMS_MAX 2000000
#define N_MOL_MAX   50000

#define K_DIM   128
#define N_DIM   64
#define TILE_M  128
#define GRID_P  304          // 2 blocks per SM on 152-SM GB300
#define NSTAGES 4
#define CHUNK_BYTES  16384   // 128 rows x 32 f32 (128B/row, SW128)
#define CHUNK_FLOATS 4096

// smem float offsets
#define BF_OFF    16384      // after 4 x 4096-float X stages
#define B1_OFF    26624
#define W2_OFF    26688
#define MBAR_OFF  26752      // 4 x u64
#define SMEM_FLOATS 26760

// scratch (no device allocation allowed)
__device__ float g_atom_out[N_ATOMS_MAX];

__device__ __forceinline__ uint32_t f2tf32(float f) {
    uint32_t u;
    asm("cvt.rna.tf32.f32 %0, %1;" : "=r"(u) : "f"(f));
    return u;
}
__device__ __forceinline__ float silu(float v) {
    return __fdividef(v, 1.0f + __expf(-v));
}
__device__ __forceinline__ void mbar_init(uint32_t mb, uint32_t cnt) {
    asm volatile("mbarrier.init.shared.b64 [%0], %1;" :: "r"(mb), "r"(cnt) : "memory");
}
__device__ __forceinline__ void mbar_wait(uint32_t mb, uint32_t phase) {
    asm volatile(
        "{\n\t.reg .pred P;\n"
        "W%=:\n\t"
        "mbarrier.try_wait.parity.acquire.cta.shared::cta.b64 P, [%0], %1, 0x989680;\n\t"
        "@P bra D%=;\n\t"
        "bra W%=;\n"
        "D%=:\n\t}"
        :: "r"(mb), "r"(phase) : "memory");
}
#define MMA_TF32(C, A0, A1, A2, A3, B0, B1)                                   \
    asm("mma.sync.aligned.m16n8k8.row.col.f32.tf32.tf32.f32 "                 \
        "{%0,%1,%2,%3}, {%4,%5,%6,%7}, {%8,%9}, {%0,%1,%2,%3};"               \
        : "+f"(C[0]), "+f"(C[1]), "+f"(C[2]), "+f"(C[3])                      \
        : "r"(A0), "r"(A1), "r"(A2), "r"(A3), "r"(B0), "r"(B1))

// ---------------------------------------------------------------------------
// Kernel 1: persistent per-atom MLP, TMA-fed 4-deep chunk ring.
// ---------------------------------------------------------------------------
__global__ __launch_bounds__(256, 2)
void mlp_kernel(const __grid_constant__ CUtensorMap tmap,
                const float* __restrict__ W1,
                const float* __restrict__ b1,
                const float* __restrict__ W2,
                const float* __restrict__ b2,
                int n_atoms, int ntiles)
{
    extern __shared__ __align__(1024) float smem[];
    uint32_t* Bf  = (uint32_t*)(smem + BF_OFF);
    float*    b1s = smem + B1_OFF;
    float*    w2s = smem + W2_OFF;
    const uint32_t smem_base = (uint32_t)__cvta_generic_to_shared(smem);
    const uint32_t mbar_base = smem_base + MBAR_OFF * 4u;
    const uint64_t tmap_ptr  = (uint64_t)&tmap;

    const int tid  = threadIdx.x;
    const int lane = tid & 31, warp = tid >> 5;
    const int g = lane >> 2, tq = lane & 3;
    const int r0 = warp * 16;

    // ---- stage W1 once: tf32, fragment-major [kk][lane(stride 20)][nt*2+j] ----
    #pragma unroll
    for (int i = 0; i < 32; i++) {
        int e = tid + 256 * i;               // e = k*64 + n (coalesced)
        int k = e >> 6, n = e & 63;
        uint32_t v = f2tf32(W1[e]);
        int gg = n & 7, nt = n >> 3, kk = k >> 3, kb = k & 7;
        int tq2 = kb & 3, j = nt * 2 + (kb >> 2);
        Bf[kk * 640 + (gg * 4 + tq2) * 20 + j] = v;
    }
    if (tid < N_DIM) { b1s[tid] = b1[tid]; w2s[tid] = W2[tid]; }
    const float b2v = b2[0];

    const int nloc = (blockIdx.x < ntiles) ? (ntiles - blockIdx.x + GRID_P - 1) / GRID_P : 0;
    const int C = nloc * 4;                  // chunks: (tile, quarter-K)

    if (tid == 0) {
        #pragma unroll
        for (int s = 0; s < NSTAGES; s++) mbar_init(mbar_base + s * 8, 1);
        asm volatile("fence.proxy.async.shared::cta;" ::: "memory");
    }
    __syncthreads();
    if (C <= 0) return;

    // producer: issue one 16KB TMA chunk
    auto issue = [&](int cn) {
        int slot = cn & (NSTAGES - 1);
        uint32_t mb  = mbar_base + slot * 8;
        uint32_t dst = smem_base + slot * CHUNK_BYTES;
        long tile = (long)blockIdx.x + (long)(cn >> 2) * GRID_P;
        int y = (int)(tile * TILE_M);
        int x = (cn & 3) * 32;
        asm volatile("mbarrier.arrive.expect_tx.shared.b64 _, [%0], %1;"
                     :: "r"(mb), "n"(CHUNK_BYTES) : "memory");
        asm volatile("cp.async.bulk.tensor.2d.shared::cta.global.tile.mbarrier::complete_tx::bytes "
                     "[%0], [%1, {%2, %3}], [%4];"
                     :: "r"(dst), "l"(tmap_ptr), "r"(x), "r"(y), "r"(mb) : "memory");
    };

    if (tid == 0) {
        int pre = (C < NSTAGES - 1) ? C : NSTAGES - 1;
        for (int cn = 0; cn < pre; cn++) issue(cn);
    }

    // per-thread A addressing (constant across chunks)
    const int rowA = r0 + g;
    const uint32_t xm = (uint32_t)((rowA & 7) << 4);   // SW128 XOR mask (same for row+8)
    const char* smem_c = (const char*)smem;

    float acc[8][4];

    for (int c = 0; c < C; c++) {
        if (tid == 0) {
            int cn = c + NSTAGES - 1;
            if (cn < C) issue(cn);
        }
        const int slot = c & (NSTAGES - 1);
        mbar_wait(mbar_base + slot * 8, (c >> 2) & 1);

        const char* slotb = smem_c + slot * CHUNK_BYTES;
        const int q = c & 3;                 // quarter-K index

        if (q == 0) {
            #pragma unroll
            for (int nt = 0; nt < 8; nt++) {
                acc[nt][0] = 0.f; acc[nt][1] = 0.f;
                acc[nt][2] = 0.f; acc[nt][3] = 0.f;
            }
        }

        #pragma unroll
        for (int kkl = 0; kkl < 4; kkl++) {
            uint32_t cb = (uint32_t)((kkl * 8 + tq) * 4);
            const char* pr = slotb + rowA * 128;
            uint32_t a0 = f2tf32(*(const float*)(pr + (cb ^ xm)));
            uint32_t a2 = f2tf32(*(const float*)(pr + ((cb + 16) ^ xm)));
            uint32_t a1 = f2tf32(*(const float*)(pr + 1024 + (cb ^ xm)));
            uint32_t a3 = f2tf32(*(const float*)(pr + 1024 + ((cb + 16) ^ xm)));
            const uint32_t* bp = Bf + (q * 4 + kkl) * 640 + lane * 20;
            uint4 b01 = *(const uint4*)(bp);
            uint4 b23 = *(const uint4*)(bp + 4);
            uint4 b45 = *(const uint4*)(bp + 8);
            uint4 b67 = *(const uint4*)(bp + 12);
            MMA_TF32(acc[0], a0, a1, a2, a3, b01.x, b01.y);
            MMA_TF32(acc[1], a0, a1, a2, a3, b01.z, b01.w);
            MMA_TF32(acc[2], a0, a1, a2, a3, b23.x, b23.y);
            MMA_TF32(acc[3], a0, a1, a2, a3, b23.z, b23.w);
            MMA_TF32(acc[4], a0, a1, a2, a3, b45.x, b45.y);
            MMA_TF32(acc[5], a0, a1, a2, a3, b45.z, b45.w);
            MMA_TF32(acc[6], a0, a1, a2, a3, b67.x, b67.y);
            MMA_TF32(acc[7], a0, a1, a2, a3, b67.z, b67.w);
        }

        if (q == 3) {
            // epilogue: +b1, silu, dot W2, reduce over tq lanes, store
            float sA = 0.f, sB = 0.f;
            #pragma unroll
            for (int nt = 0; nt < 8; nt++) {
                int col0 = nt * 8 + tq * 2;
                int col1 = col0 + 1;
                sA += silu(acc[nt][0] + b1s[col0]) * w2s[col0];
                sA += silu(acc[nt][1] + b1s[col1]) * w2s[col1];
                sB += silu(acc[nt][2] + b1s[col0]) * w2s[col0];
                sB += silu(acc[nt][3] + b1s[col1]) * w2s[col1];
            }
            sA += __shfl_xor_sync(0xFFFFFFFFu, sA, 1);
            sA += __shfl_xor_sync(0xFFFFFFFFu, sA, 2);
            sB += __shfl_xor_sync(0xFFFFFFFFu, sB, 1);
            sB += __shfl_xor_sync(0xFFFFFFFFu, sB, 2);
            if (tq == 0) {
                long tile = (long)blockIdx.x + (long)(c >> 2) * GRID_P;
                long rA = tile * TILE_M + r0 + g;
                long rB = rA + 8;
                if (rA < n_atoms) g_atom_out[rA] = sA + b2v;
                if (rB < n_atoms) g_atom_out[rB] = sB + b2v;
            }
        }
        __syncthreads();   // slot free for reuse
    }
}

// ---------------------------------------------------------------------------
// Kernel 2 (fused): per-molecule segment sum + correction + final writes.
// Deterministic: one thread per molecule, sequential sum over sorted segment.
// ---------------------------------------------------------------------------
__global__ void seg_out_kernel(const int* __restrict__ batch,
                               const float* __restrict__ charge,
                               float* __restrict__ out,
                               int n_atoms, int n_mol)
{
    int m = blockIdx.x * blockDim.x + threadIdx.x;
    if (m >= n_mol) return;
    int lo = 0, hi = n_atoms;
    while (lo < hi) {
        int mid = (lo + hi) >> 1;
        if (batch[mid] < m) lo = mid + 1; else hi = mid;
    }
    float s = 0.f;
    int i = lo;
    while (i < n_atoms && batch[i] == m) { s += g_atom_out[i]; i++; }
    int cnt = i - lo;
    if (cnt > 0) {
        float corr = (charge[m] - s) / (float)cnt;
        for (int j = lo; j < i; j++) out[j] = g_atom_out[j] + corr;
    }
}

// ---------------------------------------------------------------------------
typedef CUresult (CUDAAPI *encode_fn_t)(
    CUtensorMap*, CUtensorMapDataType, cuuint32_t, void*,
    const cuuint64_t*, const cuuint64_t*, const cuuint32_t*, const cuuint32_t*,
    CUtensorMapInterleave, CUtensorMapSwizzle, CUtensorMapL2promotion,
    CUtensorMapFloatOOBfill);

extern "C" void kernel_launch(void* const* d_in, const int* in_sizes, int n_in,
                              void* d_out, int out_size)
{
    const float* x      = (const float*)d_in[0];
    const int*   batch  = (const int*)  d_in[1];
    const float* charge = (const float*)d_in[2];
    const float* W1     = (const float*)d_in[3];
    const float* b1     = (const float*)d_in[4];
    const float* W2     = (const float*)d_in[5];
    const float* b2     = (const float*)d_in[6];
    float* out = (float*)d_out;

    const int n_atoms = in_sizes[0] / K_DIM;
    const int n_mol   = in_sizes[2];
    const int ntiles  = (n_atoms + TILE_M - 1) / TILE_M;

    static encode_fn_t encode = nullptr;
    if (!encode) {
        void* fn = nullptr;
        cudaDriverEntryPointQueryResult qr;
        cudaGetDriverEntryPoint("cuTensorMapEncodeTiled", &fn,
                                cudaEnableDefault, &qr);
        encode = (encode_fn_t)fn;
    }

    CUtensorMap tmap;
    cuuint64_t dims[2]    = {(cuuint64_t)K_DIM, (cuuint64_t)n_atoms};
    cuuint64_t strides[1] = {(cuuint64_t)K_DIM * 4};
    cuuint32_t box[2]     = {32u, 128u};
    cuuint32_t es[2]      = {1u, 1u};
    encode(&tmap, CU_TENSOR_MAP_DATA_TYPE_FLOAT32, 2, (void*)x,
           dims, strides, box, es,
           CU_TENSOR_MAP_INTERLEAVE_NONE, CU_TENSOR_MAP_SWIZZLE_128B,
           CU_TENSOR_MAP_L2_PROMOTION_L2_128B, CU_TENSOR_MAP_FLOAT_OOB_FILL_NONE);

    const int smem_bytes = SMEM_FLOATS * 4;
    cudaFuncSetAttribute(mlp_kernel, cudaFuncAttributeMaxDynamicSharedMemorySize,
                         smem_bytes);

    mlp_kernel<<<GRID_P, 256, smem_bytes>>>(tmap, W1, b1, W2, b2, n_atoms, ntiles);
    seg_out_kernel<<<(n_mol + 255) / 256, 256>>>(batch, charge, out, n_atoms, n_mol);
}

// round 5
// speedup vs baseline: 1.5794x; 1.1339x over previous
#include <cuda_runtime.h>
#include <cuda.h>
#include <cstdint>

#define N_ATOMS_MAX 2000000
#define N_MOL_MAX   50000

#define K_DIM   128
#define N_DIM   64
#define TILE_M  128
#define GRID_P  304          // 2 blocks per SM on 152-SM GB300
#define NSTAGES 4
#define CHUNK_BYTES  16384   // 128 rows x 32 f32 (128B/row, SW128)

// smem float offsets
#define BF_OFF     16384     // after 4 x 4096-float X stages
#define B1_OFF     26624
#define W2_OFF     26688
#define FULL_OFF   26752     // 4 x u64
#define EMPTY_OFF  26760     // 4 x u64
#define SMEM_FLOATS 26768

// scratch (no device allocation allowed)
__device__ float g_atom_out[N_ATOMS_MAX];
__device__ int   g_start[N_MOL_MAX + 1];

__device__ __forceinline__ uint32_t f2tf32(float f) {
    uint32_t u;
    asm("cvt.rna.tf32.f32 %0, %1;" : "=r"(u) : "f"(f));
    return u;
}
__device__ __forceinline__ float silu(float v) {
    return __fdividef(v, 1.0f + __expf(-v));
}
__device__ __forceinline__ void mbar_init(uint32_t mb, uint32_t cnt) {
    asm volatile("mbarrier.init.shared.b64 [%0], %1;" :: "r"(mb), "r"(cnt) : "memory");
}
__device__ __forceinline__ void mbar_wait(uint32_t mb, uint32_t phase) {
    asm volatile(
        "{\n\t.reg .pred P;\n"
        "W%=:\n\t"
        "mbarrier.try_wait.parity.acquire.cta.shared::cta.b64 P, [%0], %1, 0x989680;\n\t"
        "@P bra D%=;\n\t"
        "bra W%=;\n"
        "D%=:\n\t}"
        :: "r"(mb), "r"(phase) : "memory");
}
__device__ __forceinline__ void mbar_arrive(uint32_t mb) {
    asm volatile("mbarrier.arrive.shared.b64 _, [%0];" :: "r"(mb) : "memory");
}
#define MMA_TF32(C, A0, A1, A2, A3, B0, B1)                                   \
    asm("mma.sync.aligned.m16n8k8.row.col.f32.tf32.tf32.f32 "                 \
        "{%0,%1,%2,%3}, {%4,%5,%6,%7}, {%8,%9}, {%0,%1,%2,%3};"               \
        : "+f"(C[0]), "+f"(C[1]), "+f"(C[2]), "+f"(C[3])                      \
        : "r"(A0), "r"(A1), "r"(A2), "r"(A3), "r"(B0), "r"(B1))

// ---------------------------------------------------------------------------
// Kernel 1: persistent per-atom MLP, TMA-fed 4-deep ring, mbarrier-only sync.
// ---------------------------------------------------------------------------
__global__ __launch_bounds__(256, 2)
void mlp_kernel(const __grid_constant__ CUtensorMap tmap,
                const float* __restrict__ W1,
                const float* __restrict__ b1,
                const float* __restrict__ W2,
                const float* __restrict__ b2,
                int n_atoms, int ntiles)
{
    extern __shared__ __align__(1024) float smem[];
    uint32_t* Bf  = (uint32_t*)(smem + BF_OFF);
    float*    b1s = smem + B1_OFF;
    float*    w2s = smem + W2_OFF;
    const uint32_t smem_base  = (uint32_t)__cvta_generic_to_shared(smem);
    const uint32_t full_base  = smem_base + FULL_OFF * 4u;
    const uint32_t empty_base = smem_base + EMPTY_OFF * 4u;
    const uint64_t tmap_ptr   = (uint64_t)&tmap;

    const int tid  = threadIdx.x;
    const int lane = tid & 31, warp = tid >> 5;
    const int g = lane >> 2, tq = lane & 3;
    const int r0 = warp * 16;

    // ---- stage W1 once: tf32, fragment-major [kk][lane(stride 20)][nt*2+j] ----
    #pragma unroll
    for (int i = 0; i < 32; i++) {
        int e = tid + 256 * i;               // e = k*64 + n (coalesced)
        int k = e >> 6, n = e & 63;
        uint32_t v = f2tf32(W1[e]);
        int gg = n & 7, nt = n >> 3, kk = k >> 3, kb = k & 7;
        int tq2 = kb & 3, j = nt * 2 + (kb >> 2);
        Bf[kk * 640 + (gg * 4 + tq2) * 20 + j] = v;
    }
    if (tid < N_DIM) { b1s[tid] = b1[tid]; w2s[tid] = W2[tid]; }
    const float b2v = b2[0];

    const int nloc = (blockIdx.x < ntiles) ? (ntiles - blockIdx.x + GRID_P - 1) / GRID_P : 0;
    const int C = nloc * 4;                  // chunks: (tile, quarter-K)

    if (tid == 0) {
        #pragma unroll
        for (int s = 0; s < NSTAGES; s++) {
            mbar_init(full_base  + s * 8, 1);
            mbar_init(empty_base + s * 8, 8);
        }
        asm volatile("fence.proxy.async.shared::cta;" ::: "memory");
    }
    __syncthreads();
    if (C <= 0) return;

    // producer: issue one 16KB TMA chunk into slot cn%4
    auto issue = [&](int cn) {
        int slot = cn & (NSTAGES - 1);
        if (cn >= NSTAGES)                                  // wait slot consumed
            mbar_wait(empty_base + slot * 8, ((cn >> 2) + 1) & 1);
        uint32_t mb  = full_base + slot * 8;
        uint32_t dst = smem_base + slot * CHUNK_BYTES;
        long tile = (long)blockIdx.x + (long)(cn >> 2) * GRID_P;
        int y = (int)(tile * TILE_M);
        int x = (cn & 3) * 32;
        asm volatile("mbarrier.arrive.expect_tx.shared.b64 _, [%0], %1;"
                     :: "r"(mb), "n"(CHUNK_BYTES) : "memory");
        asm volatile("cp.async.bulk.tensor.2d.shared::cta.global.tile.mbarrier::complete_tx::bytes "
                     "[%0], [%1, {%2, %3}], [%4];"
                     :: "r"(dst), "l"(tmap_ptr), "r"(x), "r"(y), "r"(mb) : "memory");
    };

    if (tid == 0) {
        int pre = (C < NSTAGES - 1) ? C : NSTAGES - 1;
        for (int cn = 0; cn < pre; cn++) issue(cn);
    }

    // per-thread A addressing (constant across chunks)
    const int rowA = r0 + g;
    const uint32_t xm = (uint32_t)((rowA & 7) << 4);   // SW128 XOR mask (same for row+8)
    const char* smem_c = (const char*)smem;

    float acc[8][4];

    for (int c = 0; c < C; c++) {
        if (tid == 0) {
            int cn = c + NSTAGES - 1;
            if (cn < C) issue(cn);
        }
        const int slot = c & (NSTAGES - 1);
        mbar_wait(full_base + slot * 8, (c >> 2) & 1);

        const char* slotb = smem_c + slot * CHUNK_BYTES;
        const int q = c & 3;                 // quarter-K index

        if (q == 0) {
            #pragma unroll
            for (int nt = 0; nt < 8; nt++) {
                acc[nt][0] = 0.f; acc[nt][1] = 0.f;
                acc[nt][2] = 0.f; acc[nt][3] = 0.f;
            }
        }

        #pragma unroll
        for (int kkl = 0; kkl < 4; kkl++) {
            uint32_t cb = (uint32_t)((kkl * 8 + tq) * 4);
            const char* pr = slotb + rowA * 128;
            uint32_t a0 = f2tf32(*(const float*)(pr + (cb ^ xm)));
            uint32_t a2 = f2tf32(*(const float*)(pr + ((cb + 16) ^ xm)));
            uint32_t a1 = f2tf32(*(const float*)(pr + 1024 + (cb ^ xm)));
            uint32_t a3 = f2tf32(*(const float*)(pr + 1024 + ((cb + 16) ^ xm)));
            const uint32_t* bp = Bf + (q * 4 + kkl) * 640 + lane * 20;
            uint4 b01 = *(const uint4*)(bp);
            uint4 b23 = *(const uint4*)(bp + 4);
            uint4 b45 = *(const uint4*)(bp + 8);
            uint4 b67 = *(const uint4*)(bp + 12);
            MMA_TF32(acc[0], a0, a1, a2, a3, b01.x, b01.y);
            MMA_TF32(acc[1], a0, a1, a2, a3, b01.z, b01.w);
            MMA_TF32(acc[2], a0, a1, a2, a3, b23.x, b23.y);
            MMA_TF32(acc[3], a0, a1, a2, a3, b23.z, b23.w);
            MMA_TF32(acc[4], a0, a1, a2, a3, b45.x, b45.y);
            MMA_TF32(acc[5], a0, a1, a2, a3, b45.z, b45.w);
            MMA_TF32(acc[6], a0, a1, a2, a3, b67.x, b67.y);
            MMA_TF32(acc[7], a0, a1, a2, a3, b67.z, b67.w);
        }

        // signal slot consumed (one arrive per warp; LDS data already in regs)
        if (lane == 0) mbar_arrive(empty_base + slot * 8);

        if (q == 3) {
            // epilogue: +b1, silu, dot W2, reduce over tq lanes, store
            float sA = 0.f, sB = 0.f;
            #pragma unroll
            for (int nt = 0; nt < 8; nt++) {
                int col0 = nt * 8 + tq * 2;
                int col1 = col0 + 1;
                sA += silu(acc[nt][0] + b1s[col0]) * w2s[col0];
                sA += silu(acc[nt][1] + b1s[col1]) * w2s[col1];
                sB += silu(acc[nt][2] + b1s[col0]) * w2s[col0];
                sB += silu(acc[nt][3] + b1s[col1]) * w2s[col1];
            }
            sA += __shfl_xor_sync(0xFFFFFFFFu, sA, 1);
            sA += __shfl_xor_sync(0xFFFFFFFFu, sA, 2);
            sB += __shfl_xor_sync(0xFFFFFFFFu, sB, 1);
            sB += __shfl_xor_sync(0xFFFFFFFFu, sB, 2);
            if (tq == 0) {
                long tile = (long)blockIdx.x + (long)(c >> 2) * GRID_P;
                long rA = tile * TILE_M + r0 + g;
                long rB = rA + 8;
                if (rA < n_atoms) g_atom_out[rA] = sA + b2v;
                if (rB < n_atoms) g_atom_out[rB] = sB + b2v;
            }
        }
    }
}

// ---------------------------------------------------------------------------
// Kernel 2: segment boundary detection over sorted batch (coalesced).
// g_start[m] = first atom index with batch[i] >= m;  g_start[n_mol] = n_atoms.
// ---------------------------------------------------------------------------
__global__ void bounds_kernel(const int* __restrict__ batch, int n_atoms, int n_mol)
{
    int i = blockIdx.x * blockDim.x + threadIdx.x;
    if (i >= n_atoms) return;
    int b = batch[i];
    if (i == 0) {
        for (int m = 0; m <= b; m++) g_start[m] = 0;
    } else {
        int p = batch[i - 1];
        for (int m = p + 1; m <= b; m++) g_start[m] = i;
    }
    if (i == n_atoms - 1) {
        for (int m = b + 1; m <= n_mol; m++) g_start[m] = n_atoms;
    }
}

// ---------------------------------------------------------------------------
// Kernel 3: warp per molecule — coalesced segment sum, correction, and
// final segment-contiguous writes. Deterministic (fixed reduction order).
// ---------------------------------------------------------------------------
__global__ void seg_out_kernel(const float* __restrict__ charge,
                               float* __restrict__ out, int n_mol)
{
    int w    = (blockIdx.x * blockDim.x + threadIdx.x) >> 5;
    int lane = threadIdx.x & 31;
    if (w >= n_mol) return;
    int s = g_start[w], e = g_start[w + 1];
    int cnt = e - s;
    if (cnt <= 0) return;
    float sum = 0.f;
    for (int i = s + lane; i < e; i += 32) sum += g_atom_out[i];
    #pragma unroll
    for (int o = 16; o; o >>= 1) sum += __shfl_xor_sync(0xFFFFFFFFu, sum, o);
    float corr = (charge[w] - sum) / (float)cnt;
    for (int i = s + lane; i < e; i += 32) out[i] = g_atom_out[i] + corr;
}

// ---------------------------------------------------------------------------
typedef CUresult (CUDAAPI *encode_fn_t)(
    CUtensorMap*, CUtensorMapDataType, cuuint32_t, void*,
    const cuuint64_t*, const cuuint64_t*, const cuuint32_t*, const cuuint32_t*,
    CUtensorMapInterleave, CUtensorMapSwizzle, CUtensorMapL2promotion,
    CUtensorMapFloatOOBfill);

extern "C" void kernel_launch(void* const* d_in, const int* in_sizes, int n_in,
                              void* d_out, int out_size)
{
    const float* x      = (const float*)d_in[0];
    const int*   batch  = (const int*)  d_in[1];
    const float* charge = (const float*)d_in[2];
    const float* W1     = (const float*)d_in[3];
    const float* b1     = (const float*)d_in[4];
    const float* W2     = (const float*)d_in[5];
    const float* b2     = (const float*)d_in[6];
    float* out = (float*)d_out;

    const int n_atoms = in_sizes[0] / K_DIM;
    const int n_mol   = in_sizes[2];
    const int ntiles  = (n_atoms + TILE_M - 1) / TILE_M;

    static encode_fn_t encode = nullptr;
    if (!encode) {
        void* fn = nullptr;
        cudaDriverEntryPointQueryResult qr;
        cudaGetDriverEntryPoint("cuTensorMapEncodeTiled", &fn,
                                cudaEnableDefault, &qr);
        encode = (encode_fn_t)fn;
    }

    CUtensorMap tmap;
    cuuint64_t dims[2]    = {(cuuint64_t)K_DIM, (cuuint64_t)n_atoms};
    cuuint64_t strides[1] = {(cuuint64_t)K_DIM * 4};
    cuuint32_t box[2]     = {32u, 128u};
    cuuint32_t es[2]      = {1u, 1u};
    encode(&tmap, CU_TENSOR_MAP_DATA_TYPE_FLOAT32, 2, (void*)x,
           dims, strides, box, es,
           CU_TENSOR_MAP_INTERLEAVE_NONE, CU_TENSOR_MAP_SWIZZLE_128B,
           CU_TENSOR_MAP_L2_PROMOTION_L2_128B, CU_TENSOR_MAP_FLOAT_OOB_FILL_NONE);

    const int smem_bytes = SMEM_FLOATS * 4;
    cudaFuncSetAttribute(mlp_kernel, cudaFuncAttributeMaxDynamicSharedMemorySize,
                         smem_bytes);

    mlp_kernel<<<GRID_P, 256, smem_bytes>>>(tmap, W1, b1, W2, b2, n_atoms, ntiles);
    bounds_kernel<<<(n_atoms + 255) / 256, 256>>>(batch, n_atoms, n_mol);
    seg_out_kernel<<<(n_mol * 32 + 255) / 256, 256>>>(charge, out, n_mol);
}